// round 1
// baseline (speedup 1.0000x reference)
#include <cuda_runtime.h>
#include <cstdint>

// Problem constants
#define D_MODEL 192
#define D_INNER 384
#define D_STATE 16
#define DT_RANK 12
#define BB 2
#define HH 64
#define WW 64
#define LL 4096            // HH*WW
#define MM (BB*LL)         // 8192 rows

// ---------------- scratch (no allocations allowed) ----------------
__device__ float g_xa   [MM*D_INNER];  // pre-conv xa (NHWC)
__device__ float g_z    [MM*D_INNER];  // silu(z)
__device__ float g_c    [MM*D_INNER];  // pre-conv condition proj
__device__ float g_u    [MM*D_INNER];  // silu(conv(xa))  == u (orig pixel order)
__device__ float g_s    [MM*D_INNER];  // u + silu(conv(c)) (orig pixel order)
__device__ float g_delta[MM*D_INNER];  // delta, scan order [b*L+l, d]
__device__ float g_bc   [MM*32];       // B (0..15) and C (16..31), scan order
__device__ float g_y    [MM*D_INNER];  // scan output, ORIGINAL pixel order
__device__ float g_g    [MM*D_INNER];  // post-LN * z

__device__ __forceinline__ float silu_f(float x) { return x / (1.f + __expf(-x)); }
__device__ __forceinline__ float softplus_f(float x) {
    return fmaxf(x, 0.f) + log1pf(__expf(-fabsf(x)));
}

// ---------------- K1: fused input GEMMs ----------------
// C[m,n] = A[m,:] . W[n,:],  n<768 -> (x, W_in), n>=768 -> (cond, W_con)
// epilogue routes to g_xa / g_z(silu) / g_c
__global__ __launch_bounds__(256) void k1_gemm(
    const float* __restrict__ x, const float* __restrict__ cond,
    const float* __restrict__ Win, const float* __restrict__ Wcon)
{
    __shared__ float As[16][68];
    __shared__ float Ws[16][68];
    const int n0 = blockIdx.x * 64;
    const int m0 = blockIdx.y * 64;
    const int tid = threadIdx.x;
    const bool is_c = (n0 >= 768);
    const float* A = is_c ? cond : x;
    const float* W = is_c ? (Wcon + (size_t)(n0 - 768) * D_MODEL)
                          : (Win  + (size_t)n0 * D_MODEL);
    const int K = D_MODEL;
    const int tx = tid & 15, ty = tid >> 4;
    const int ml = tid >> 2, kl = (tid & 3) * 4;
    float acc[4][4] = {};

    for (int k0 = 0; k0 < K; k0 += 16) {
        float4 a4 = *(const float4*)&A[(size_t)(m0 + ml) * K + k0 + kl];
        float4 w4 = *(const float4*)&W[(size_t)ml * K + k0 + kl];
        __syncthreads();
        As[kl+0][ml] = a4.x; As[kl+1][ml] = a4.y; As[kl+2][ml] = a4.z; As[kl+3][ml] = a4.w;
        Ws[kl+0][ml] = w4.x; Ws[kl+1][ml] = w4.y; Ws[kl+2][ml] = w4.z; Ws[kl+3][ml] = w4.w;
        __syncthreads();
        #pragma unroll
        for (int kk = 0; kk < 16; kk++) {
            float4 av = *(const float4*)&As[kk][ty*4];
            float4 bv = *(const float4*)&Ws[kk][tx*4];
            float a[4] = {av.x, av.y, av.z, av.w};
            float b[4] = {bv.x, bv.y, bv.z, bv.w};
            #pragma unroll
            for (int i = 0; i < 4; i++)
                #pragma unroll
                for (int j = 0; j < 4; j++)
                    acc[i][j] += a[i] * b[j];
        }
    }
    #pragma unroll
    for (int i = 0; i < 4; i++) {
        int m = m0 + ty*4 + i;
        #pragma unroll
        for (int j = 0; j < 4; j++) {
            int n = n0 + tx*4 + j;
            float v = acc[i][j];
            if (n < 384)       g_xa[m*D_INNER + n] = v;
            else if (n < 768)  g_z [m*D_INNER + (n-384)] = silu_f(v);
            else               g_c [m*D_INNER + (n-768)] = v;
        }
    }
}

// ---------------- K2: depthwise 3x3 conv (SAME) + bias + silu, both branches ----------------
__global__ __launch_bounds__(384) void k2_conv(
    const float* __restrict__ cw, const float* __restrict__ cb,
    const float* __restrict__ ccw, const float* __restrict__ ccb)
{
    const int m = blockIdx.x;
    const int d = threadIdx.x;
    const int b = m >> 12, rem = m & 4095, h = rem >> 6, w = rem & 63;
    float ax = 0.f, ac = 0.f;
    #pragma unroll
    for (int dh = -1; dh <= 1; dh++) {
        int h2 = h + dh; if (h2 < 0 || h2 >= HH) continue;
        #pragma unroll
        for (int dw = -1; dw <= 1; dw++) {
            int w2 = w + dw; if (w2 < 0 || w2 >= WW) continue;
            int mi = ((b << 12) + (h2 << 6) + w2) * D_INNER + d;
            int ki = d * 9 + (dh + 1) * 3 + (dw + 1);
            ax += g_xa[mi] * cw[ki];
            ac += g_c [mi] * ccw[ki];
        }
    }
    float uv = silu_f(ax + cb[d]);
    float cv = silu_f(ac + ccb[d]);
    g_u[m*D_INNER + d] = uv;
    g_s[m*D_INNER + d] = uv + cv;
}

// ---------------- K3: gather(perm) -> x_dbl (44) -> delta(softplus) + B/C ----------------
__global__ __launch_bounds__(384) void k3_proj(
    const float* __restrict__ xpw,   // [44,384]
    const float* __restrict__ dtw,   // [384,12]
    const float* __restrict__ dtb,   // [384]
    const int*   __restrict__ perm)  // [4096]
{
    __shared__ float sv[D_INNER];
    __shared__ float part[44][9];
    __shared__ float xd[44];
    const int ml = blockIdx.x;            // scan index b*L + l
    const int b = ml >> 12, l = ml & 4095;
    const int t = threadIdx.x;
    const int p = perm[l];
    sv[t] = g_s[((b << 12) + p) * D_INNER + t];
    __syncthreads();
    if (t < 352) {
        const int c = t >> 3, seg = t & 7;
        const float* wr = xpw + c * D_INNER + seg * 48;
        const float* s2 = sv + seg * 48;
        float a = 0.f;
        #pragma unroll
        for (int i = 0; i < 48; i++) a += wr[i] * s2[i];
        part[c][seg] = a;
    }
    __syncthreads();
    if (t < 44) {
        float a = 0.f;
        #pragma unroll
        for (int i = 0; i < 8; i++) a += part[t][i];
        xd[t] = a;
    }
    __syncthreads();
    float acc = dtb[t];
    #pragma unroll
    for (int r = 0; r < DT_RANK; r++) acc += xd[r] * dtw[t * DT_RANK + r];
    g_delta[ml * D_INNER + t] = softplus_f(acc);
    if (t < 32) g_bc[ml * 32 + t] = xd[12 + t];   // B = xd[12..27], C = xd[28..43]
}

// ---------------- K4: selective scan. warp = (b,d), lane = state ----------------
__global__ __launch_bounds__(128) void k4_scan(
    const float* __restrict__ Alogs, const float* __restrict__ Ds,
    const int* __restrict__ perm)
{
    const int g = blockIdx.x * 4 + (threadIdx.x >> 5);
    const int lane = threadIdx.x & 31;
    const int b = g / D_INNER, d = g % D_INNER;
    const float Al = (lane < 16) ? -__expf(Alogs[d * 16 + lane]) : 0.f;
    const float Dd = Ds[d];
    float h = 0.f;
    const float* bcP = g_bc    + (size_t)b * LL * 32;
    const float* dlP = g_delta + (size_t)b * LL * D_INNER + d;
    const float* uP  = g_u     + (size_t)b * LL * D_INNER + d;
    float*       yP  = g_y     + (size_t)b * LL * D_INNER + d;

    #pragma unroll 4
    for (int l = 0; l < LL; l++) {
        float bc = __ldg(bcP + l * 32 + lane);
        float de = __ldg(dlP + (size_t)l * D_INNER);
        int   p  = __ldg(perm + l);
        float u  = __ldg(uP + (size_t)p * D_INNER);
        float a  = __expf(de * Al);
        float Cv = __shfl_sync(0xffffffffu, bc, lane + 16);
        h = a * h + de * bc * u;              // lanes>=16 harmless
        float pr = h * Cv;
        pr += __shfl_xor_sync(0xffffffffu, pr, 8);
        pr += __shfl_xor_sync(0xffffffffu, pr, 4);
        pr += __shfl_xor_sync(0xffffffffu, pr, 2);
        pr += __shfl_xor_sync(0xffffffffu, pr, 1);
        if (lane == 0) yP[(size_t)p * D_INNER] = pr + u * Dd;  // fused un-permute
    }
}

// ---------------- K5: LayerNorm over D_INNER, then * silu(z) ----------------
__global__ __launch_bounds__(384) void k5_ln(
    const float* __restrict__ lnw, const float* __restrict__ lnb)
{
    __shared__ float red0[12], red1[12];
    const int m = blockIdx.x, t = threadIdx.x;
    float v = g_y[m * D_INNER + t];
    float s = v, s2 = v * v;
    #pragma unroll
    for (int o = 16; o; o >>= 1) {
        s  += __shfl_xor_sync(0xffffffffu, s,  o);
        s2 += __shfl_xor_sync(0xffffffffu, s2, o);
    }
    if ((t & 31) == 0) { red0[t >> 5] = s; red1[t >> 5] = s2; }
    __syncthreads();
    if (t < 32) {
        float a = (t < 12) ? red0[t] : 0.f;
        float c = (t < 12) ? red1[t] : 0.f;
        #pragma unroll
        for (int o = 16; o; o >>= 1) {
            a += __shfl_xor_sync(0xffffffffu, a, o);
            c += __shfl_xor_sync(0xffffffffu, c, o);
        }
        if (t == 0) { red0[0] = a; red1[0] = c; }
    }
    __syncthreads();
    const float mu  = red0[0] * (1.f / D_INNER);
    const float var = red1[0] * (1.f / D_INNER) - mu * mu;
    const float r = rsqrtf(var + 1e-5f);
    float out = (v - mu) * r * lnw[t] + lnb[t];
    g_g[m * D_INNER + t] = out * g_z[m * D_INNER + t];
}

// ---------------- K6: output GEMM [8192,384]x[192,384]^T ----------------
__global__ __launch_bounds__(256) void k6_gemm(
    const float* __restrict__ Wout, float* __restrict__ out)
{
    __shared__ float As[16][68];
    __shared__ float Ws[16][68];
    const int n0 = blockIdx.x * 64;
    const int m0 = blockIdx.y * 64;
    const int tid = threadIdx.x;
    const int K = D_INNER;
    const int tx = tid & 15, ty = tid >> 4;
    const int ml = tid >> 2, kl = (tid & 3) * 4;
    float acc[4][4] = {};

    for (int k0 = 0; k0 < K; k0 += 16) {
        float4 a4 = *(const float4*)&g_g [(size_t)(m0 + ml) * K + k0 + kl];
        float4 w4 = *(const float4*)&Wout[(size_t)(n0 + ml) * K + k0 + kl];
        __syncthreads();
        As[kl+0][ml] = a4.x; As[kl+1][ml] = a4.y; As[kl+2][ml] = a4.z; As[kl+3][ml] = a4.w;
        Ws[kl+0][ml] = w4.x; Ws[kl+1][ml] = w4.y; Ws[kl+2][ml] = w4.z; Ws[kl+3][ml] = w4.w;
        __syncthreads();
        #pragma unroll
        for (int kk = 0; kk < 16; kk++) {
            float4 av = *(const float4*)&As[kk][ty*4];
            float4 bv = *(const float4*)&Ws[kk][tx*4];
            float a[4] = {av.x, av.y, av.z, av.w};
            float b[4] = {bv.x, bv.y, bv.z, bv.w};
            #pragma unroll
            for (int i = 0; i < 4; i++)
                #pragma unroll
                for (int j = 0; j < 4; j++)
                    acc[i][j] += a[i] * b[j];
        }
    }
    #pragma unroll
    for (int i = 0; i < 4; i++) {
        int m = m0 + ty*4 + i;
        #pragma unroll
        for (int j = 0; j < 4; j++) {
            int n = n0 + tx*4 + j;
            out[(size_t)m * D_MODEL + n] = acc[i][j];
        }
    }
}

// ---------------- launch ----------------
extern "C" void kernel_launch(void* const* d_in, const int* in_sizes, int n_in,
                              void* d_out, int out_size)
{
    const float* x      = (const float*)d_in[0];
    const float* cond   = (const float*)d_in[1];
    const float* Win    = (const float*)d_in[2];
    const float* Wcon   = (const float*)d_in[3];
    const float* convw  = (const float*)d_in[4];
    const float* convb  = (const float*)d_in[5];
    const float* cconvw = (const float*)d_in[6];
    const float* cconvb = (const float*)d_in[7];
    const float* xpw    = (const float*)d_in[8];
    const float* dtw    = (const float*)d_in[9];
    const float* dtb    = (const float*)d_in[10];
    const float* Alogs  = (const float*)d_in[11];
    const float* DsP    = (const float*)d_in[12];
    const float* lnw    = (const float*)d_in[13];
    const float* lnb    = (const float*)d_in[14];
    const float* Wout   = (const float*)d_in[15];
    const int*   perm   = (const int*)d_in[16];
    // d_in[17] = rev_scan_path: unused (un-permute fused into scan store)

    k1_gemm<<<dim3(1152/64, MM/64), 256>>>(x, cond, Win, Wcon);
    k2_conv<<<MM, 384>>>(convw, convb, cconvw, cconvb);
    k3_proj<<<MM, 384>>>(xpw, dtw, dtb, perm);
    k4_scan<<<(BB * D_INNER) / 4, 128>>>(Alogs, DsP, perm);
    k5_ln<<<MM, 384>>>(lnw, lnb);
    k6_gemm<<<dim3(D_MODEL/64, MM/64), 256>>>(Wout, (float*)d_out);
}

// round 3
// speedup vs baseline: 2.2208x; 2.2208x over previous
#include <cuda_runtime.h>
#include <cstdint>

// Problem constants
#define D_MODEL 192
#define D_INNER 384
#define D_STATE 16
#define DT_RANK 12
#define BB 2
#define HH 64
#define WW 64
#define LL 4096            // HH*WW
#define MM (BB*LL)         // 8192 rows
#define GG (BB*D_INNER)    // 768 sequences
#define NC 32              // chunks per sequence
#define CL (LL/NC)         // 128 steps per chunk

// ---------------- scratch (no allocations allowed) ----------------
__device__ float g_xa   [MM*D_INNER];
__device__ float g_z    [MM*D_INNER];
__device__ float g_c    [MM*D_INNER];
__device__ float g_u    [MM*D_INNER];
__device__ float g_s    [MM*D_INNER];
__device__ float g_delta[MM*D_INNER];
__device__ float g_bc   [MM*32];
__device__ float g_y    [MM*D_INNER];
__device__ float g_g    [MM*D_INNER];
// chunk summaries
__device__ float g_hF[GG*NC*16];
__device__ float g_P [GG*NC*16];
__device__ float g_hI[GG*NC*16];

__device__ __forceinline__ float silu_f(float x) { return x / (1.f + __expf(-x)); }
__device__ __forceinline__ float softplus_f(float x) {
    return fmaxf(x, 0.f) + log1pf(__expf(-fabsf(x)));
}

// ---------------- K1: fused input GEMMs ----------------
__global__ __launch_bounds__(256) void k1_gemm(
    const float* __restrict__ x, const float* __restrict__ cond,
    const float* __restrict__ Win, const float* __restrict__ Wcon)
{
    __shared__ float As[16][68];
    __shared__ float Ws[16][68];
    const int n0 = blockIdx.x * 64;
    const int m0 = blockIdx.y * 64;
    const int tid = threadIdx.x;
    const bool is_c = (n0 >= 768);
    const float* A = is_c ? cond : x;
    const float* W = is_c ? (Wcon + (size_t)(n0 - 768) * D_MODEL)
                          : (Win  + (size_t)n0 * D_MODEL);
    const int K = D_MODEL;
    const int tx = tid & 15, ty = tid >> 4;
    const int ml = tid >> 2, kl = (tid & 3) * 4;
    float acc[4][4] = {};

    for (int k0 = 0; k0 < K; k0 += 16) {
        float4 a4 = *(const float4*)&A[(size_t)(m0 + ml) * K + k0 + kl];
        float4 w4 = *(const float4*)&W[(size_t)ml * K + k0 + kl];
        __syncthreads();
        As[kl+0][ml] = a4.x; As[kl+1][ml] = a4.y; As[kl+2][ml] = a4.z; As[kl+3][ml] = a4.w;
        Ws[kl+0][ml] = w4.x; Ws[kl+1][ml] = w4.y; Ws[kl+2][ml] = w4.z; Ws[kl+3][ml] = w4.w;
        __syncthreads();
        #pragma unroll
        for (int kk = 0; kk < 16; kk++) {
            float4 av = *(const float4*)&As[kk][ty*4];
            float4 bv = *(const float4*)&Ws[kk][tx*4];
            float a[4] = {av.x, av.y, av.z, av.w};
            float b[4] = {bv.x, bv.y, bv.z, bv.w};
            #pragma unroll
            for (int i = 0; i < 4; i++)
                #pragma unroll
                for (int j = 0; j < 4; j++)
                    acc[i][j] += a[i] * b[j];
        }
    }
    #pragma unroll
    for (int i = 0; i < 4; i++) {
        int m = m0 + ty*4 + i;
        #pragma unroll
        for (int j = 0; j < 4; j++) {
            int n = n0 + tx*4 + j;
            float v = acc[i][j];
            if (n < 384)       g_xa[m*D_INNER + n] = v;
            else if (n < 768)  g_z [m*D_INNER + (n-384)] = silu_f(v);
            else               g_c [m*D_INNER + (n-768)] = v;
        }
    }
}

// ---------------- K2: depthwise 3x3 conv + bias + silu ----------------
__global__ __launch_bounds__(384) void k2_conv(
    const float* __restrict__ cw, const float* __restrict__ cb,
    const float* __restrict__ ccw, const float* __restrict__ ccb)
{
    const int m = blockIdx.x;
    const int d = threadIdx.x;
    const int b = m >> 12, rem = m & 4095, h = rem >> 6, w = rem & 63;
    float ax = 0.f, ac = 0.f;
    #pragma unroll
    for (int dh = -1; dh <= 1; dh++) {
        int h2 = h + dh; if (h2 < 0 || h2 >= HH) continue;
        #pragma unroll
        for (int dw = -1; dw <= 1; dw++) {
            int w2 = w + dw; if (w2 < 0 || w2 >= WW) continue;
            int mi = ((b << 12) + (h2 << 6) + w2) * D_INNER + d;
            int ki = d * 9 + (dh + 1) * 3 + (dw + 1);
            ax += g_xa[mi] * cw[ki];
            ac += g_c [mi] * ccw[ki];
        }
    }
    float uv = silu_f(ax + cb[d]);
    float cv = silu_f(ac + ccb[d]);
    g_u[m*D_INNER + d] = uv;
    g_s[m*D_INNER + d] = uv + cv;
}

// ---------------- K3: tiled gather + x_dbl + delta + B/C ----------------
// block handles R3=16 scan rows; weights reused across the tile
#define R3 16
__global__ __launch_bounds__(384) void k3_proj(
    const float* __restrict__ xpw,   // [44,384]
    const float* __restrict__ dtw,   // [384,12]
    const float* __restrict__ dtb,   // [384]
    const int*   __restrict__ perm)  // [4096]
{
    __shared__ float sv[R3][D_INNER];   // 24KB
    __shared__ float xd[R3][48];        // 3KB
    const int r0 = blockIdx.x * R3;     // base scan row (over MM)
    const int t = threadIdx.x;

    // stage 1: gather 16 rows of s into smem
    #pragma unroll
    for (int r = 0; r < R3; r++) {
        int ml = r0 + r;
        int b = ml >> 12, l = ml & 4095;
        int p = __ldg(perm + l);
        sv[r][t] = __ldg(&g_s[((size_t)((b << 12) + p)) * D_INNER + t]);
    }
    __syncthreads();

    // stage 2: x_dbl = sv @ xpw^T  -> xd[16][44]
    #pragma unroll
    for (int pass = 0; pass < 2; pass++) {
        int e = t + pass * 384;
        if (e < R3 * 44) {
            int row = e / 44, c = e % 44;
            const float4* wv = (const float4*)(xpw + (size_t)c * D_INNER);
            const float4* s4 = (const float4*)(&sv[row][0]);
            float a = 0.f;
            #pragma unroll
            for (int k = 0; k < D_INNER/4; k++) {
                float4 w4 = __ldg(&wv[k]);
                float4 s_ = s4[k];
                a += w4.x*s_.x + w4.y*s_.y + w4.z*s_.z + w4.w*s_.w;
            }
            xd[row][c] = a;
        }
    }
    __syncthreads();

    // stage 3: delta = softplus(xd[:, :12] @ dtw^T + dtb)  (thread t = channel d)
    {
        float wreg[DT_RANK];
        #pragma unroll
        for (int j = 0; j < DT_RANK; j++) wreg[j] = __ldg(&dtw[t * DT_RANK + j]);
        float bias = __ldg(&dtb[t]);
        #pragma unroll
        for (int r = 0; r < R3; r++) {
            float acc = bias;
            #pragma unroll
            for (int j = 0; j < DT_RANK; j++) acc += xd[r][j] * wreg[j];
            g_delta[(size_t)(r0 + r) * D_INNER + t] = softplus_f(acc);
        }
    }

    // stage 4: B/C out
    for (int idx = t; idx < R3 * 32; idx += 384) {
        int r = idx >> 5, j = idx & 31;
        g_bc[(size_t)(r0 + r) * 32 + j] = xd[r][12 + j];
    }
}

// ---------------- K4a: chunk scan pass (h0 = 0), store hF and decay product P ----------------
__global__ __launch_bounds__(256) void k4a(
    const float* __restrict__ Alogs, const int* __restrict__ perm)
{
    const int w = blockIdx.x * 8 + (threadIdx.x >> 5);   // w = chunk*GG + g
    const int lane = threadIdx.x & 31;
    const int chunk = w / GG;
    const int g = w % GG;
    const int b = g / D_INNER, d = g % D_INNER;
    const float Al = (lane < 16) ? -__expf(__ldg(&Alogs[d * 16 + lane])) : 0.f;

    const int l0 = chunk * CL;
    const float* bcP = g_bc    + (size_t)(b * LL + l0) * 32;
    const float* dlP = g_delta + (size_t)(b * LL + l0) * D_INNER + d;
    const float* uP  = g_u     + (size_t)b * LL * D_INNER + d;
    const int*  prP  = perm + l0;

    float h = 0.f, P = 1.f;
    #pragma unroll 4
    for (int l = 0; l < CL; l++) {
        float Bv = (lane < 16) ? __ldg(bcP + l * 32 + lane) : 0.f;
        float de = __ldg(dlP + (size_t)l * D_INNER);
        int   p  = __ldg(prP + l);
        float u  = __ldg(uP + (size_t)p * D_INNER);
        float a  = __expf(de * Al);
        h = a * h + (de * Bv) * u;
        P *= a;
    }
    if (lane < 16) {
        g_hF[(g * NC + chunk) * 16 + lane] = h;
        g_P [(g * NC + chunk) * 16 + lane] = P;
    }
}

// ---------------- K4b: serial combine over chunk summaries ----------------
__global__ __launch_bounds__(256) void k4b()
{
    const int g = blockIdx.x * 8 + (threadIdx.x >> 5);
    const int lane = threadIdx.x & 31;
    if (lane < 16) {
        float h = 0.f;
        #pragma unroll
        for (int c = 0; c < NC; c++) {
            int i = (g * NC + c) * 16 + lane;
            g_hI[i] = h;
            h = g_P[i] * h + g_hF[i];
        }
    }
}

// ---------------- K4c: final chunk scan with correct h0, batched reductions ----------------
__global__ __launch_bounds__(256) void k4c(
    const float* __restrict__ Alogs, const float* __restrict__ Ds,
    const int* __restrict__ perm)
{
    const int w = blockIdx.x * 8 + (threadIdx.x >> 5);
    const int lane = threadIdx.x & 31;
    const int chunk = w / GG;
    const int g = w % GG;
    const int b = g / D_INNER, d = g % D_INNER;
    const float Al = (lane < 16) ? -__expf(__ldg(&Alogs[d * 16 + lane])) : 0.f;
    const float Dd = __ldg(&Ds[d]);

    const int l0 = chunk * CL;
    const float* bcP = g_bc    + (size_t)(b * LL + l0) * 32;
    const float* dlP = g_delta + (size_t)(b * LL + l0) * D_INNER + d;
    const float* uP  = g_u     + (size_t)b * LL * D_INNER + d;
    float*       yP  = g_y     + (size_t)b * LL * D_INNER + d;
    const int*  prP  = perm + l0;

    float h = (lane < 16) ? g_hI[(g * NC + chunk) * 16 + lane] : 0.f;

    for (int l4 = 0; l4 < CL; l4 += 4) {
        float pr[4], uu[4];
        int   pp[4];
        #pragma unroll
        for (int j = 0; j < 4; j++) {
            int l = l4 + j;
            float bc = __ldg(bcP + l * 32 + lane);
            float de = __ldg(dlP + (size_t)l * D_INNER);
            int   p  = __ldg(prP + l);
            float u  = __ldg(uP + (size_t)p * D_INNER);
            float a  = __expf(de * Al);
            float Cv = __shfl_sync(0xffffffffu, bc, lane + 16);
            h = a * h + (de * bc) * u;
            pr[j] = h * Cv; uu[j] = u; pp[j] = p;
        }
        #pragma unroll
        for (int j = 0; j < 4; j++) {
            float s = pr[j];
            s += __shfl_xor_sync(0xffffffffu, s, 8);
            s += __shfl_xor_sync(0xffffffffu, s, 4);
            s += __shfl_xor_sync(0xffffffffu, s, 2);
            s += __shfl_xor_sync(0xffffffffu, s, 1);
            if (lane == 0) yP[(size_t)pp[j] * D_INNER] = s + uu[j] * Dd;
        }
    }
}

// ---------------- K5: LayerNorm over D_INNER, then * silu(z) ----------------
__global__ __launch_bounds__(384) void k5_ln(
    const float* __restrict__ lnw, const float* __restrict__ lnb)
{
    __shared__ float red0[12], red1[12];
    const int m = blockIdx.x, t = threadIdx.x;
    float v = g_y[m * D_INNER + t];
    float s = v, s2 = v * v;
    #pragma unroll
    for (int o = 16; o; o >>= 1) {
        s  += __shfl_xor_sync(0xffffffffu, s,  o);
        s2 += __shfl_xor_sync(0xffffffffu, s2, o);
    }
    if ((t & 31) == 0) { red0[t >> 5] = s; red1[t >> 5] = s2; }
    __syncthreads();
    if (t < 32) {
        float a = (t < 12) ? red0[t] : 0.f;
        float c = (t < 12) ? red1[t] : 0.f;
        #pragma unroll
        for (int o = 16; o; o >>= 1) {
            a += __shfl_xor_sync(0xffffffffu, a, o);
            c += __shfl_xor_sync(0xffffffffu, c, o);
        }
        if (t == 0) { red0[0] = a; red1[0] = c; }
    }
    __syncthreads();
    const float mu  = red0[0] * (1.f / D_INNER);
    const float var = red1[0] * (1.f / D_INNER) - mu * mu;
    const float r = rsqrtf(var + 1e-5f);
    float out = (v - mu) * r * lnw[t] + lnb[t];
    g_g[m * D_INNER + t] = out * g_z[m * D_INNER + t];
}

// ---------------- K6: output GEMM ----------------
__global__ __launch_bounds__(256) void k6_gemm(
    const float* __restrict__ Wout, float* __restrict__ out)
{
    __shared__ float As[16][68];
    __shared__ float Ws[16][68];
    const int n0 = blockIdx.x * 64;
    const int m0 = blockIdx.y * 64;
    const int tid = threadIdx.x;
    const int K = D_INNER;
    const int tx = tid & 15, ty = tid >> 4;
    const int ml = tid >> 2, kl = (tid & 3) * 4;
    float acc[4][4] = {};

    for (int k0 = 0; k0 < K; k0 += 16) {
        float4 a4 = *(const float4*)&g_g [(size_t)(m0 + ml) * K + k0 + kl];
        float4 w4 = *(const float4*)&Wout[(size_t)(n0 + ml) * K + k0 + kl];
        __syncthreads();
        As[kl+0][ml] = a4.x; As[kl+1][ml] = a4.y; As[kl+2][ml] = a4.z; As[kl+3][ml] = a4.w;
        Ws[kl+0][ml] = w4.x; Ws[kl+1][ml] = w4.y; Ws[kl+2][ml] = w4.z; Ws[kl+3][ml] = w4.w;
        __syncthreads();
        #pragma unroll
        for (int kk = 0; kk < 16; kk++) {
            float4 av = *(const float4*)&As[kk][ty*4];
            float4 bv = *(const float4*)&Ws[kk][tx*4];
            float a[4] = {av.x, av.y, av.z, av.w};
            float b[4] = {bv.x, bv.y, bv.z, bv.w};
            #pragma unroll
            for (int i = 0; i < 4; i++)
                #pragma unroll
                for (int j = 0; j < 4; j++)
                    acc[i][j] += a[i] * b[j];
        }
    }
    #pragma unroll
    for (int i = 0; i < 4; i++) {
        int m = m0 + ty*4 + i;
        #pragma unroll
        for (int j = 0; j < 4; j++) {
            int n = n0 + tx*4 + j;
            out[(size_t)m * D_MODEL + n] = acc[i][j];
        }
    }
}

// ---------------- launch ----------------
extern "C" void kernel_launch(void* const* d_in, const int* in_sizes, int n_in,
                              void* d_out, int out_size)
{
    const float* x      = (const float*)d_in[0];
    const float* cond   = (const float*)d_in[1];
    const float* Win    = (const float*)d_in[2];
    const float* Wcon   = (const float*)d_in[3];
    const float* convw  = (const float*)d_in[4];
    const float* convb  = (const float*)d_in[5];
    const float* cconvw = (const float*)d_in[6];
    const float* cconvb = (const float*)d_in[7];
    const float* xpw    = (const float*)d_in[8];
    const float* dtw    = (const float*)d_in[9];
    const float* dtb    = (const float*)d_in[10];
    const float* Alogs  = (const float*)d_in[11];
    const float* DsP    = (const float*)d_in[12];
    const float* lnw    = (const float*)d_in[13];
    const float* lnb    = (const float*)d_in[14];
    const float* Wout   = (const float*)d_in[15];
    const int*   perm   = (const int*)d_in[16];

    k1_gemm<<<dim3(1152/64, MM/64), 256>>>(x, cond, Win, Wcon);
    k2_conv<<<MM, 384>>>(convw, convb, cconvw, cconvb);
    k3_proj<<<MM/R3, 384>>>(xpw, dtw, dtb, perm);
    k4a<<<(GG*NC)/8, 256>>>(Alogs, perm);
    k4b<<<GG/8, 256>>>();
    k4c<<<(GG*NC)/8, 256>>>(Alogs, DsP, perm);
    k5_ln<<<MM, 384>>>(lnw, lnb);
    k6_gemm<<<dim3(D_MODEL/64, MM/64), 256>>>(Wout, (float*)d_out);
}